// round 2
// baseline (speedup 1.0000x reference)
#include <cuda_runtime.h>
#include <stdint.h>
#include <math.h>

#define N_NODES 50000
#define N_EDGES 800000
#define F_IN    128
#define HID     256
#define N_OUT   10
#define N_G     128
#define T_STEPS 15

// ---------------- device scratch (static: no runtime allocation) ----------------
__device__ unsigned d_xtbits[(size_t)T_STEPS * N_NODES * 4];   // 12 MB, bitpacked x_t
__device__ float    d_agg[(size_t)N_NODES * F_IN];             // 25.6 MB
__device__ float    d_v[(size_t)N_NODES * HID];                // 51.2 MB
__device__ float    d_S[(size_t)N_NODES * HID];                // 51.2 MB
__device__ int      d_degcnt[N_NODES];
__device__ int      d_rowptr[N_NODES + 1];
__device__ int      d_cursor[N_NODES];
__device__ int      d_colsrc[N_EDGES];
__device__ float    d_invdeg[N_NODES];
__device__ float    d_invsqrt[N_NODES];
__device__ int      d_gcnt[N_G];
__device__ float    d_invcnt[N_G];
__device__ float    d_M[HID * N_OUT];
__device__ float    d_y[(size_t)N_NODES * N_OUT];
__device__ float    d_P[N_G * N_OUT];

struct Keys { unsigned k0[T_STEPS]; unsigned k1[T_STEPS]; };

// ---------------- threefry (host, for the 15 subkeys) ----------------
static void threefry_pair_host(uint32_t k0, uint32_t k1, uint32_t x0, uint32_t x1,
                               uint32_t* o0, uint32_t* o1) {
    uint32_t ks2 = k0 ^ k1 ^ 0x1BD11BDAu;
    x0 += k0; x1 += k1;
#define HR(R) { x0 += x1; x1 = (x1 << R) | (x1 >> (32 - R)); x1 ^= x0; }
    HR(13) HR(15) HR(26) HR(6)
    x0 += k1; x1 += ks2 + 1u;
    HR(17) HR(29) HR(16) HR(24)
    x0 += ks2; x1 += k0 + 2u;
    HR(13) HR(15) HR(26) HR(6)
    x0 += k0; x1 += k1 + 3u;
    HR(17) HR(29) HR(16) HR(24)
    x0 += k1; x1 += ks2 + 4u;
    HR(13) HR(15) HR(26) HR(6)
    x0 += ks2; x1 += k0 + 5u;
#undef HR
    *o0 = x0; *o1 = x1;
}

// ---------------- init (zero all per-call state) ----------------
__global__ void init_kernel() {
    const int total = N_NODES * HID;
    for (int i = blockIdx.x * blockDim.x + threadIdx.x; i < total;
         i += gridDim.x * blockDim.x) {
        d_v[i] = 0.f;
        d_S[i] = 0.f;
        if (i < N_NODES) { d_degcnt[i] = 0; d_cursor[i] = 0; }
        if (i < N_G)     { d_gcnt[i] = 0; }
        if (i < N_G * N_OUT) { d_P[i] = 0.f; }
    }
}

__global__ void count_deg(const int* __restrict__ dst) {
    int e = blockIdx.x * blockDim.x + threadIdx.x;
    if (e < N_EDGES) atomicAdd(&d_degcnt[dst[e]], 1);
}

__global__ void count_batch(const int* __restrict__ batch) {
    int n = blockIdx.x * blockDim.x + threadIdx.x;
    if (n < N_NODES) atomicAdd(&d_gcnt[batch[n]], 1);
}

__global__ void node_prep() {
    int n = blockIdx.x * blockDim.x + threadIdx.x;
    if (n >= N_NODES) return;
    int c = d_degcnt[n];
    int cm = c > 1 ? c : 1;
    d_invdeg[n] = 1.0f / (float)cm;
    d_invsqrt[n] = 1.0f / sqrtf((float)(c + 1));   // deg2 includes self-loop
}

__global__ void graph_prep() {
    int g = threadIdx.x;
    if (g < N_G) {
        int c = d_gcnt[g];
        d_invcnt[g] = 1.0f / (float)(c > 1 ? c : 1);
    }
}

// exclusive scan of d_degcnt -> d_rowptr, single block
__global__ void scan_kernel() {
    __shared__ int sh[1024];
    __shared__ int carry_s;
    int tid = threadIdx.x;
    if (tid == 0) carry_s = 0;
    __syncthreads();
    for (int base = 0; base < N_NODES; base += 1024) {
        int i = base + tid;
        int v = (i < N_NODES) ? d_degcnt[i] : 0;
        sh[tid] = v;
        __syncthreads();
        for (int off = 1; off < 1024; off <<= 1) {
            int t2 = (tid >= off) ? sh[tid - off] : 0;
            __syncthreads();
            sh[tid] += t2;
            __syncthreads();
        }
        int carry = carry_s;
        if (i < N_NODES) d_rowptr[i] = carry + sh[tid] - v;
        __syncthreads();
        if (tid == 1023) carry_s = carry + sh[1023];
        __syncthreads();
    }
    if (tid == 0) d_rowptr[N_NODES] = carry_s;
}

__global__ void csr_fill(const int* __restrict__ src, const int* __restrict__ dst) {
    int e = blockIdx.x * blockDim.x + threadIdx.x;
    if (e >= N_EDGES) return;
    int d = dst[e];
    int p = atomicAdd(&d_cursor[d], 1);
    d_colsrc[d_rowptr[d] + p] = src[e];
}

// ---------------- RNG: JAX threefry2x32 (partitionable), bitpacked Bernoulli ----------------
#define DR(R) { x0 += x1; x1 = __funnelshift_l(x1, x1, R); x1 ^= x0; }

__global__ void rng_kernel(const float* __restrict__ x, Keys keys) {
    int gid = blockIdx.x * blockDim.x + threadIdx.x;
    const int total = T_STEPS * N_NODES * 4;
    if (gid >= total) return;
    int w  = gid & 3;
    int nw = gid >> 2;
    int n  = nw % N_NODES;
    int t  = nw / N_NODES;
    const unsigned k0 = keys.k0[t];
    const unsigned k1 = keys.k1[t];
    const unsigned ks2 = k0 ^ k1 ^ 0x1BD11BDAu;
    const unsigned base = (unsigned)(n * F_IN + w * 32);
    const float* xr = x + n * F_IN + w * 32;
    unsigned outw = 0u;
    #pragma unroll 4
    for (int b = 0; b < 32; b++) {
        unsigned x0 = k0;               // counts1 = 0 (+ k0)
        unsigned x1 = base + (unsigned)b + k1;
        DR(13) DR(15) DR(26) DR(6)
        x0 += k1;  x1 += ks2 + 1u;
        DR(17) DR(29) DR(16) DR(24)
        x0 += ks2; x1 += k0 + 2u;
        DR(13) DR(15) DR(26) DR(6)
        x0 += k0;  x1 += k1 + 3u;
        DR(17) DR(29) DR(16) DR(24)
        x0 += k1;  x1 += ks2 + 4u;
        DR(13) DR(15) DR(26) DR(6)
        x0 += ks2; x1 += k0 + 5u;
        unsigned bits = x0 ^ x1;        // partitionable 32-bit path
        float u = __uint_as_float((bits >> 9) | 0x3f800000u) - 1.0f;
        if (u < xr[b]) outw |= (1u << b);
    }
    d_xtbits[gid] = outw;
}
#undef DR

// ---------------- per-step: aggregate bitpacked spikes over in-edges ----------------
__global__ void agg_kernel(int t) {
    int gw = (blockIdx.x * blockDim.x + threadIdx.x) >> 5;
    int lane = threadIdx.x & 31;
    if (gw >= N_NODES) return;
    int beg = d_rowptr[gw], end = d_rowptr[gw + 1];
    const uint4* xb = (const uint4*)(d_xtbits + (size_t)t * N_NODES * 4);
    int c0 = 0, c1 = 0, c2 = 0, c3 = 0;
    for (int e = beg; e < end; e++) {
        int s = d_colsrc[e];
        uint4 wv = __ldg(&xb[s]);
        c0 += (wv.x >> lane) & 1;
        c1 += (wv.y >> lane) & 1;
        c2 += (wv.z >> lane) & 1;
        c3 += (wv.w >> lane) & 1;
    }
    float idg = d_invdeg[gw];
    float* a = d_agg + (size_t)gw * F_IN;
    a[lane]      = (float)c0 * idg;
    a[32 + lane] = (float)c1 * idg;
    a[64 + lane] = (float)c2 * idg;
    a[96 + lane] = (float)c3 * idg;
}

// ---------------- per-step: h = agg @ W1, fused LIF update ----------------
__global__ __launch_bounds__(256, 2) void gemm_lif_kernel(const float* __restrict__ W1) {
    __shared__ float As[16][128];
    __shared__ float Bs[16][128];
    const int ftile = blockIdx.x;          // 0 or 1 (feature half)
    const int node0 = blockIdx.y * 128;
    const int tid = threadIdx.x;
    const int tx = tid & 15, ty = tid >> 4;

    float acc[8][8];
    #pragma unroll
    for (int i = 0; i < 8; i++)
        #pragma unroll
        for (int j = 0; j < 8; j++) acc[i][j] = 0.f;

    const int am = tid >> 1;
    const int ak = (tid & 1) * 8;
    const int bk = tid >> 4;
    const int bc = (tid & 15) * 8;
    const int an = node0 + am;
    const float* aptr = d_agg + (size_t)an * F_IN + ak;
    const float* bptr = W1 + bk * HID + ftile * 128 + bc;

    for (int k0 = 0; k0 < F_IN; k0 += 16) {
        float4 a0, a1;
        if (an < N_NODES) {
            a0 = *(const float4*)(aptr + k0);
            a1 = *(const float4*)(aptr + k0 + 4);
        } else {
            a0 = make_float4(0.f, 0.f, 0.f, 0.f); a1 = a0;
        }
        As[ak + 0][am] = a0.x; As[ak + 1][am] = a0.y;
        As[ak + 2][am] = a0.z; As[ak + 3][am] = a0.w;
        As[ak + 4][am] = a1.x; As[ak + 5][am] = a1.y;
        As[ak + 6][am] = a1.z; As[ak + 7][am] = a1.w;

        float4 b0 = *(const float4*)(bptr + k0 * HID);
        float4 b1 = *(const float4*)(bptr + k0 * HID + 4);
        *(float4*)&Bs[bk][bc]     = b0;
        *(float4*)&Bs[bk][bc + 4] = b1;
        __syncthreads();

        #pragma unroll
        for (int k = 0; k < 16; k++) {
            float ar[8], br[8];
            *(float4*)(ar)     = *(const float4*)&As[k][ty * 8];
            *(float4*)(ar + 4) = *(const float4*)&As[k][ty * 8 + 4];
            *(float4*)(br)     = *(const float4*)&Bs[k][tx * 8];
            *(float4*)(br + 4) = *(const float4*)&Bs[k][tx * 8 + 4];
            #pragma unroll
            for (int i = 0; i < 8; i++)
                #pragma unroll
                for (int j = 0; j < 8; j++)
                    acc[i][j] += ar[i] * br[j];
        }
        __syncthreads();
    }

    // fused LIF epilogue: v += (h - v)/2; s = (v >= 0.25); v reset; S += s
    const int featBase = ftile * 128 + tx * 8;
    #pragma unroll
    for (int i = 0; i < 8; i++) {
        int n = node0 + ty * 8 + i;
        if (n >= N_NODES) continue;
        float* vp = d_v + (size_t)n * HID + featBase;
        float* Sp = d_S + (size_t)n * HID + featBase;
        float4 v0 = *(float4*)(vp), v1 = *(float4*)(vp + 4);
        float4 S0 = *(float4*)(Sp), S1 = *(float4*)(Sp + 4);
#define LIF(VC, SC, HC) { float vn = VC + (HC - VC) * 0.5f;                    \
                          if (vn >= 0.25f) { SC += 1.0f; vn = 0.0f; }          \
                          VC = vn; }
        LIF(v0.x, S0.x, acc[i][0]) LIF(v0.y, S0.y, acc[i][1])
        LIF(v0.z, S0.z, acc[i][2]) LIF(v0.w, S0.w, acc[i][3])
        LIF(v1.x, S1.x, acc[i][4]) LIF(v1.y, S1.y, acc[i][5])
        LIF(v1.z, S1.z, acc[i][6]) LIF(v1.w, S1.w, acc[i][7])
#undef LIF
        *(float4*)(vp)     = v0; *(float4*)(vp + 4) = v1;
        *(float4*)(Sp)     = S0; *(float4*)(Sp + 4) = S1;
    }
}

// ---------------- readout: M = W2 @ Wlin ----------------
__global__ void mk_kernel(const float* __restrict__ W2, const float* __restrict__ Wlin) {
    int h = threadIdx.x;  // 256 threads
    float acc[N_OUT];
    #pragma unroll
    for (int c = 0; c < N_OUT; c++) acc[c] = 0.f;
    for (int k = 0; k < HID; k++) {
        float w = W2[h * HID + k];
        #pragma unroll
        for (int c = 0; c < N_OUT; c++) acc[c] += w * Wlin[k * N_OUT + c];
    }
    #pragma unroll
    for (int c = 0; c < N_OUT; c++) d_M[h * N_OUT + c] = acc[c];
}

// y = S @ M  ([N,256]@[256,10])
__global__ void y_kernel() {
    __shared__ float Ms[HID * N_OUT];
    for (int i = threadIdx.x; i < HID * N_OUT; i += blockDim.x) Ms[i] = d_M[i];
    __syncthreads();
    int n = blockIdx.x * blockDim.x + threadIdx.x;
    if (n >= N_NODES) return;
    float acc[N_OUT];
    #pragma unroll
    for (int c = 0; c < N_OUT; c++) acc[c] = 0.f;
    const float* Sr = d_S + (size_t)n * HID;
    for (int h = 0; h < HID; h++) {
        float s = Sr[h];
        #pragma unroll
        for (int c = 0; c < N_OUT; c++) acc[c] += s * Ms[h * N_OUT + c];
    }
    float* yp = d_y + (size_t)n * N_OUT;
    #pragma unroll
    for (int c = 0; c < N_OUT; c++) yp[c] = acc[c];
}

// z[n] = gcn_agg(y)[n]; P[batch[n]] += z[n] * inv_cnt
__global__ void pool_kernel(const int* __restrict__ batch) {
    int n = blockIdx.x * blockDim.x + threadIdx.x;
    if (n >= N_NODES) return;
    float acc[N_OUT];
    #pragma unroll
    for (int c = 0; c < N_OUT; c++) acc[c] = 0.f;
    int beg = d_rowptr[n], end = d_rowptr[n + 1];
    for (int e = beg; e < end; e++) {
        int s = d_colsrc[e];
        float ws = d_invsqrt[s];
        const float* yp = d_y + (size_t)s * N_OUT;
        #pragma unroll
        for (int c = 0; c < N_OUT; c++) acc[c] += ws * yp[c];
    }
    float isn = d_invsqrt[n];
    const float* yn = d_y + (size_t)n * N_OUT;
    int g = batch[n];
    float sc = d_invcnt[g];
    #pragma unroll
    for (int c = 0; c < N_OUT; c++) {
        float z = acc[c] * isn + isn * isn * yn[c];
        atomicAdd(&d_P[g * N_OUT + c], z * sc);
    }
}

__global__ void final_kernel(const float* __restrict__ b2,
                             const float* __restrict__ Wlin,
                             const float* __restrict__ blin,
                             float* __restrict__ out) {
    int idx = blockIdx.x * blockDim.x + threadIdx.x;
    if (idx >= N_G * N_OUT) return;
    int c = idx % N_OUT;
    float b2w = 0.f;
    for (int k = 0; k < HID; k++) b2w += b2[k] * Wlin[k * N_OUT + c];
    out[idx] = d_P[idx] / 15.0f + b2w + blin[c];
}

// ---------------- launch ----------------
extern "C" void kernel_launch(void* const* d_in, const int* in_sizes, int n_in,
                              void* d_out, int out_size) {
    const float *x = 0, *W1 = 0, *W2 = 0, *b2 = 0, *Wlin = 0, *blin = 0;
    const int *src = 0, *dst = 0, *batch = 0;
    for (int i = 0; i < n_in; i++) {
        int s = in_sizes[i];
        void* p = d_in[i];
        if (s == N_NODES * F_IN)       x = (const float*)p;
        else if (s == F_IN * HID)      W1 = (const float*)p;
        else if (s == HID * HID)       W2 = (const float*)p;
        else if (s == HID)             b2 = (const float*)p;
        else if (s == HID * N_OUT)     Wlin = (const float*)p;
        else if (s == N_OUT)           blin = (const float*)p;
        else if (s == N_EDGES)         { if (!src) src = (const int*)p; else dst = (const int*)p; }
        else if (s == N_NODES)         batch = (const int*)p;
    }

    Keys keys;
    for (int t = 0; t < T_STEPS; t++) {
        uint32_t o0, o1;
        threefry_pair_host(0u, 42u, 0u, (uint32_t)t, &o0, &o1);  // foldlike split of key(42)
        keys.k0[t] = o0; keys.k1[t] = o1;
    }

    init_kernel<<<4096, 256>>>();
    count_deg<<<(N_EDGES + 255) / 256, 256>>>(dst);
    count_batch<<<(N_NODES + 255) / 256, 256>>>(batch);
    node_prep<<<(N_NODES + 255) / 256, 256>>>();
    graph_prep<<<1, 128>>>();
    scan_kernel<<<1, 1024>>>();
    csr_fill<<<(N_EDGES + 255) / 256, 256>>>(src, dst);

    {
        int total = T_STEPS * N_NODES * 4;
        rng_kernel<<<(total + 255) / 256, 256>>>(x, keys);
    }

    for (int t = 0; t < T_STEPS; t++) {
        agg_kernel<<<(N_NODES * 32 + 255) / 256, 256>>>(t);
        gemm_lif_kernel<<<dim3(2, (N_NODES + 127) / 128), 256>>>(W1);
    }

    mk_kernel<<<1, 256>>>(W2, Wlin);
    y_kernel<<<(N_NODES + 255) / 256, 256>>>();
    pool_kernel<<<(N_NODES + 255) / 256, 256>>>(batch);
    final_kernel<<<(N_G * N_OUT + 255) / 256, 256>>>(b2, Wlin, blin, (float*)d_out);
}

// round 4
// speedup vs baseline: 1.6400x; 1.6400x over previous
#include <cuda_runtime.h>
#include <cuda_bf16.h>
#include <stdint.h>
#include <math.h>

#define N_NODES 50000
#define N_EDGES 800000
#define F_IN    128
#define HID     256
#define N_OUT   10
#define N_G     128
#define T_STEPS 15
#define TILE    128
#define N_TILES 391   // ceil(50000/128)

// ---------------- device scratch ----------------
__device__ uint4  d_xtbits4[(size_t)T_STEPS * N_NODES];  // 12 MB bitpacked x_t
__device__ uint4  d_W1q[8192];                           // 128KB packed bf16 hi/lo fragments
__device__ int    d_degcnt[N_NODES];
__device__ int    d_rowptr[N_NODES + 1];
__device__ int    d_cursor[N_NODES];
__device__ int    d_colsrc[N_EDGES];
__device__ float  d_invdeg[N_NODES];
__device__ float  d_invsqrt[N_NODES];
__device__ int    d_gcnt[N_G];
__device__ float  d_invcnt[N_G];
__device__ float  d_M[HID * N_OUT];
__device__ float  d_y[(size_t)N_NODES * N_OUT];
__device__ float  d_P[N_G * N_OUT];

struct Keys { unsigned k0[T_STEPS]; unsigned k1[T_STEPS]; };

// ---------------- host threefry for subkeys ----------------
static void threefry_pair_host(uint32_t k0, uint32_t k1, uint32_t x0, uint32_t x1,
                               uint32_t* o0, uint32_t* o1) {
    uint32_t ks2 = k0 ^ k1 ^ 0x1BD11BDAu;
    x0 += k0; x1 += k1;
#define HR(R) { x0 += x1; x1 = (x1 << R) | (x1 >> (32 - R)); x1 ^= x0; }
    HR(13) HR(15) HR(26) HR(6)
    x0 += k1; x1 += ks2 + 1u;
    HR(17) HR(29) HR(16) HR(24)
    x0 += ks2; x1 += k0 + 2u;
    HR(13) HR(15) HR(26) HR(6)
    x0 += k0; x1 += k1 + 3u;
    HR(17) HR(29) HR(16) HR(24)
    x0 += k1; x1 += ks2 + 4u;
    HR(13) HR(15) HR(26) HR(6)
    x0 += ks2; x1 += k0 + 5u;
#undef HR
    *o0 = x0; *o1 = x1;
}

// ---------------- prep kernels ----------------
__global__ void init_kernel() {
    int i = blockIdx.x * blockDim.x + threadIdx.x;
    if (i < N_NODES) { d_degcnt[i] = 0; d_cursor[i] = 0; }
    if (i < N_G)     d_gcnt[i] = 0;
    if (i < N_G * N_OUT) d_P[i] = 0.f;
}

__global__ void count_deg(const int* __restrict__ dst) {
    int e = blockIdx.x * blockDim.x + threadIdx.x;
    if (e < N_EDGES) atomicAdd(&d_degcnt[dst[e]], 1);
}

__global__ void count_batch(const int* __restrict__ batch) {
    int n = blockIdx.x * blockDim.x + threadIdx.x;
    if (n < N_NODES) atomicAdd(&d_gcnt[batch[n]], 1);
}

__global__ void node_prep() {
    int n = blockIdx.x * blockDim.x + threadIdx.x;
    if (n >= N_NODES) return;
    int c = d_degcnt[n];
    int cm = c > 1 ? c : 1;
    d_invdeg[n] = 1.0f / (float)cm;
    d_invsqrt[n] = 1.0f / sqrtf((float)(c + 1));
}

__global__ void graph_prep() {
    int g = threadIdx.x;
    if (g < N_G) {
        int c = d_gcnt[g];
        d_invcnt[g] = 1.0f / (float)(c > 1 ? c : 1);
    }
}

__global__ void scan_kernel() {
    __shared__ int sh[1024];
    __shared__ int carry_s;
    int tid = threadIdx.x;
    if (tid == 0) carry_s = 0;
    __syncthreads();
    for (int base = 0; base < N_NODES; base += 1024) {
        int i = base + tid;
        int v = (i < N_NODES) ? d_degcnt[i] : 0;
        sh[tid] = v;
        __syncthreads();
        for (int off = 1; off < 1024; off <<= 1) {
            int t2 = (tid >= off) ? sh[tid - off] : 0;
            __syncthreads();
            sh[tid] += t2;
            __syncthreads();
        }
        int carry = carry_s;
        if (i < N_NODES) d_rowptr[i] = carry + sh[tid] - v;
        __syncthreads();
        if (tid == 1023) carry_s = carry + sh[1023];
        __syncthreads();
    }
    if (tid == 0) d_rowptr[N_NODES] = carry_s;
}

__global__ void csr_fill(const int* __restrict__ src, const int* __restrict__ dst) {
    int e = blockIdx.x * blockDim.x + threadIdx.x;
    if (e >= N_EDGES) return;
    int d = dst[e];
    int p = atomicAdd(&d_cursor[d], 1);
    d_colsrc[d_rowptr[d] + p] = src[e];
}

// ---------------- W1 pack: per (j, ks, q) -> uint4 {hi_b0, hi_b1, lo_b0, lo_b1} ----------------
__device__ __forceinline__ unsigned short f2bf_hi(float w) {
    return (unsigned short)__bfloat16_as_ushort(__float2bfloat16(w));
}

__global__ void w1pack_kernel(const float* __restrict__ W1) {
    int idx = blockIdx.x * blockDim.x + threadIdx.x;   // 8192 = 256 j * 8 ks * 4 q
    if (idx >= 8192) return;
    int q = idx & 3, ks = (idx >> 2) & 7, j = idx >> 5;
    int k0 = ks * 16;
    int ka = k0 + 2 * q;
    int kb = k0 + 8 + 2 * q;
    float wa0 = W1[ka * HID + j],       wa1 = W1[(ka + 1) * HID + j];
    float wb0 = W1[kb * HID + j],       wb1 = W1[(kb + 1) * HID + j];
    unsigned short ha0 = f2bf_hi(wa0), ha1 = f2bf_hi(wa1);
    unsigned short hb0 = f2bf_hi(wb0), hb1 = f2bf_hi(wb1);
    float ra0 = wa0 - __bfloat162float(__ushort_as_bfloat16(ha0));
    float ra1 = wa1 - __bfloat162float(__ushort_as_bfloat16(ha1));
    float rb0 = wb0 - __bfloat162float(__ushort_as_bfloat16(hb0));
    float rb1 = wb1 - __bfloat162float(__ushort_as_bfloat16(hb1));
    unsigned short la0 = f2bf_hi(ra0), la1 = f2bf_hi(ra1);
    unsigned short lb0 = f2bf_hi(rb0), lb1 = f2bf_hi(rb1);
    uint4 o;
    o.x = (unsigned)ha0 | ((unsigned)ha1 << 16);
    o.y = (unsigned)hb0 | ((unsigned)hb1 << 16);
    o.z = (unsigned)la0 | ((unsigned)la1 << 16);
    o.w = (unsigned)lb0 | ((unsigned)lb1 << 16);
    d_W1q[idx] = o;
}

// ---------------- RNG: JAX threefry2x32 partitionable ----------------
#define DR(R) { x0 += x1; x1 = __funnelshift_l(x1, x1, R); x1 ^= x0; }

__global__ void rng_kernel(const float* __restrict__ x, Keys keys) {
    int gid = blockIdx.x * blockDim.x + threadIdx.x;
    const int total = T_STEPS * N_NODES * 4;
    if (gid >= total) return;
    int w  = gid & 3;
    int nw = gid >> 2;
    int n  = nw % N_NODES;
    int t  = nw / N_NODES;
    const unsigned k0 = keys.k0[t];
    const unsigned k1 = keys.k1[t];
    const unsigned ks2 = k0 ^ k1 ^ 0x1BD11BDAu;
    const unsigned base = (unsigned)(n * F_IN + w * 32);
    const float* xr = x + n * F_IN + w * 32;
    unsigned outw = 0u;
    #pragma unroll 4
    for (int b = 0; b < 32; b++) {
        unsigned x0 = k0;
        unsigned x1 = base + (unsigned)b + k1;
        DR(13) DR(15) DR(26) DR(6)
        x0 += k1;  x1 += ks2 + 1u;
        DR(17) DR(29) DR(16) DR(24)
        x0 += ks2; x1 += k0 + 2u;
        DR(13) DR(15) DR(26) DR(6)
        x0 += k0;  x1 += k1 + 3u;
        DR(17) DR(29) DR(16) DR(24)
        x0 += k1;  x1 += ks2 + 4u;
        DR(13) DR(15) DR(26) DR(6)
        x0 += ks2; x1 += k0 + 5u;
        unsigned bits = x0 ^ x1;
        float u = __uint_as_float((bits >> 9) | 0x3f800000u) - 1.0f;
        if (u < xr[b]) outw |= (1u << b);
    }
    ((unsigned*)d_xtbits4)[gid] = outw;
}
#undef DR

// ---------------- warp-mma helpers ----------------
__device__ __forceinline__ void mma_bf16(float* d, const unsigned* a, unsigned b0, unsigned b1) {
    asm volatile(
        "mma.sync.aligned.m16n8k16.row.col.f32.bf16.bf16.f32 "
        "{%0,%1,%2,%3}, {%4,%5,%6,%7}, {%8,%9}, {%0,%1,%2,%3};"
        : "+f"(d[0]), "+f"(d[1]), "+f"(d[2]), "+f"(d[3])
        : "r"(a[0]), "r"(a[1]), "r"(a[2]), "r"(a[3]), "r"(b0), "r"(b1));
}

__device__ __forceinline__ void ldmatrix4(unsigned* r, uint32_t addr) {
    asm volatile("ldmatrix.sync.aligned.m8n8.x4.shared.b16 {%0,%1,%2,%3}, [%4];"
        : "=r"(r[0]), "=r"(r[1]), "=r"(r[2]), "=r"(r[3]) : "r"(addr));
}

// ---------------- fused time-loop megakernel ----------------
// smem: A counts bf16 [128][136]  (0 .. 34816)
//       V f32 [128][264]          (34816 .. 169984)
// after t-loop, A region reused: M [2560 f32] @0, yacc [1280 f32] @10240
#define SMO_V 34816
#define SMEM_TOTAL 169984
#define A_STRIDE 136
#define V_STRIDE 264

__global__ __launch_bounds__(512) void fused_kernel() {
    extern __shared__ char smem[];
    unsigned short* Aimg = (unsigned short*)smem;
    float* Vsm = (float*)(smem + SMO_V);
    const int tid = threadIdx.x;
    const int wid = tid >> 5, lane = tid & 31;
    const int tile0 = blockIdx.x * TILE;
    const int rg = wid >> 2, cg = wid & 3;
    const int q = lane & 3, l4 = lane >> 2;

    // zero V
    for (int i = tid; i < TILE * V_STRIDE; i += 512) Vsm[i] = 0.f;

    uint32_t sbA;
    asm("{ .reg .u64 t; cvta.to.shared.u64 t, %1; cvt.u32.u64 %0, t; }" : "=r"(sbA) : "l"(smem));

    // per-lane rows: r = rb*2 + h8 -> row = rg*32 + rb*16 + h8*8 + l4
    int lrow[4];
    float idg[4];
    #pragma unroll
    for (int r = 0; r < 4; r++) {
        int lr = rg * 32 + (r >> 1) * 16 + (r & 1) * 8 + l4;
        lrow[r] = lr;
        int n = tile0 + lr;
        idg[r] = (n < N_NODES) ? d_invdeg[n] : 0.f;
    }

    unsigned Spk[8];
    #pragma unroll
    for (int i = 0; i < 8; i++) Spk[i] = 0u;

    // ldmatrix base addresses (A fragment): row = rg*32 + rb*16 + (lane&15), koff += (lane>>4)*8
    const uint32_t aAddr0 = sbA + (uint32_t)(((rg * 32 + (lane & 15)) * A_STRIDE + (lane >> 4) * 8) * 2);
    const uint32_t aAddr1 = aAddr0 + 16 * A_STRIDE * 2;

    for (int t = 0; t < T_STEPS; t++) {
        // ---- aggregation: warp wid handles nodes [wid*8, wid*8+8) ----
        const uint4* xb = d_xtbits4 + (size_t)t * N_NODES;
        #pragma unroll 1
        for (int i = 0; i < 8; i++) {
            int m = wid * 8 + i;
            int n = tile0 + m;
            int c0 = 0, c1 = 0, c2 = 0, c3 = 0;
            if (n < N_NODES) {
                int beg = __ldg(&d_rowptr[n]), end = __ldg(&d_rowptr[n + 1]);
                int e = beg;
                for (; e + 4 <= end; e += 4) {
                    int s0 = __ldg(&d_colsrc[e]),     s1 = __ldg(&d_colsrc[e + 1]);
                    int s2 = __ldg(&d_colsrc[e + 2]), s3 = __ldg(&d_colsrc[e + 3]);
                    uint4 w0 = __ldg(xb + s0), w1 = __ldg(xb + s1);
                    uint4 w2 = __ldg(xb + s2), w3 = __ldg(xb + s3);
                    c0 += ((w0.x >> lane) & 1) + ((w1.x >> lane) & 1) + ((w2.x >> lane) & 1) + ((w3.x >> lane) & 1);
                    c1 += ((w0.y >> lane) & 1) + ((w1.y >> lane) & 1) + ((w2.y >> lane) & 1) + ((w3.y >> lane) & 1);
                    c2 += ((w0.z >> lane) & 1) + ((w1.z >> lane) & 1) + ((w2.z >> lane) & 1) + ((w3.z >> lane) & 1);
                    c3 += ((w0.w >> lane) & 1) + ((w1.w >> lane) & 1) + ((w2.w >> lane) & 1) + ((w3.w >> lane) & 1);
                }
                for (; e < end; e++) {
                    uint4 wv = __ldg(xb + __ldg(&d_colsrc[e]));
                    c0 += (wv.x >> lane) & 1;
                    c1 += (wv.y >> lane) & 1;
                    c2 += (wv.z >> lane) & 1;
                    c3 += (wv.w >> lane) & 1;
                }
            }
            // exact small ints -> bf16 (truncation is exact for |c| < 256)
            Aimg[m * A_STRIDE + lane]      = (unsigned short)(__float_as_uint((float)c0) >> 16);
            Aimg[m * A_STRIDE + 32 + lane] = (unsigned short)(__float_as_uint((float)c1) >> 16);
            Aimg[m * A_STRIDE + 64 + lane] = (unsigned short)(__float_as_uint((float)c2) >> 16);
            Aimg[m * A_STRIDE + 96 + lane] = (unsigned short)(__float_as_uint((float)c3) >> 16);
        }
        __syncthreads();

        // ---- warp GEMM: 32 rows x 64 cols, K=128, hi+lo ----
        float acc[2][8][4];
        #pragma unroll
        for (int rb = 0; rb < 2; rb++)
            #pragma unroll
            for (int nt = 0; nt < 8; nt++)
                #pragma unroll
                for (int k = 0; k < 4; k++) acc[rb][nt][k] = 0.f;

        #pragma unroll
        for (int ks = 0; ks < 8; ks++) {
            unsigned a0[4], a1[4];
            ldmatrix4(a0, aAddr0 + (uint32_t)(ks * 32));   // 16 bf16 cols = 32 bytes per ks
            ldmatrix4(a1, aAddr1 + (uint32_t)(ks * 32));
            #pragma unroll
            for (int nt = 0; nt < 8; nt++) {
                int j = cg * 64 + nt * 8 + l4;
                uint4 B = __ldg(&d_W1q[(j * 8 + ks) * 4 + q]);
                mma_bf16(acc[0][nt], a0, B.x, B.y);
                mma_bf16(acc[1][nt], a1, B.x, B.y);
                mma_bf16(acc[0][nt], a0, B.z, B.w);
                mma_bf16(acc[1][nt], a1, B.z, B.w);
            }
        }

        // ---- LIF epilogue: v in smem (float2), S as 4-bit reg counters ----
        #pragma unroll
        for (int rb = 0; rb < 2; rb++) {
            #pragma unroll
            for (int nt = 0; nt < 8; nt++) {
                #pragma unroll
                for (int h8 = 0; h8 < 2; h8++) {
                    const int r = rb * 2 + h8;
                    float2* vp = (float2*)&Vsm[lrow[r] * V_STRIDE + cg * 64 + nt * 8 + q * 2];
                    float2 v = *vp;
                    float h0 = acc[rb][nt][h8 * 2 + 0] * idg[r];
                    float h1 = acc[rb][nt][h8 * 2 + 1] * idg[r];
                    float vn0 = v.x + (h0 - v.x) * 0.5f;
                    float vn1 = v.y + (h1 - v.y) * 0.5f;
                    const int slot0 = r * 16 + nt * 2;
                    if (vn0 >= 0.25f) { Spk[slot0 >> 3] += 1u << ((slot0 & 7) * 4); vn0 = 0.f; }
                    const int slot1 = slot0 + 1;
                    if (vn1 >= 0.25f) { Spk[slot1 >> 3] += 1u << ((slot1 & 7) * 4); vn1 = 0.f; }
                    *vp = make_float2(vn0, vn1);
                }
            }
        }
        __syncthreads();
    }

    // ---- fused readout: y = S @ M ----
    float* Msm  = (float*)smem;               // 2560 f32 (A region is dead)
    float* yacc = (float*)(smem + 10240);     // 1280 f32
    for (int i = tid; i < HID * N_OUT; i += 512) Msm[i] = d_M[i];
    for (int i = tid; i < TILE * N_OUT; i += 512) yacc[i] = 0.f;
    __syncthreads();

    #pragma unroll
    for (int r = 0; r < 4; r++) {
        float py[N_OUT];
        #pragma unroll
        for (int c = 0; c < N_OUT; c++) py[c] = 0.f;
        #pragma unroll
        for (int nt = 0; nt < 8; nt++) {
            #pragma unroll
            for (int p = 0; p < 2; p++) {
                const int slot = r * 16 + nt * 2 + p;
                float s = (float)((Spk[slot >> 3] >> ((slot & 7) * 4)) & 15u);
                const float* Mr = Msm + (cg * 64 + nt * 8 + q * 2 + p) * N_OUT;
                #pragma unroll
                for (int c = 0; c < N_OUT; c++) py[c] += s * Mr[c];
            }
        }
        #pragma unroll
        for (int c = 0; c < N_OUT; c++) {
            py[c] += __shfl_xor_sync(0xFFFFFFFFu, py[c], 1);
            py[c] += __shfl_xor_sync(0xFFFFFFFFu, py[c], 2);
        }
        if (q == 0) {
            #pragma unroll
            for (int c = 0; c < N_OUT; c++)
                atomicAdd(&yacc[lrow[r] * N_OUT + c], py[c]);
        }
    }
    __syncthreads();

    for (int i = tid; i < TILE * N_OUT; i += 512) {
        int node = tile0 + i / N_OUT;
        if (node < N_NODES) d_y[(size_t)node * N_OUT + (i % N_OUT)] = yacc[i];
    }
}

// ---------------- readout helpers ----------------
__global__ void mk_kernel(const float* __restrict__ W2, const float* __restrict__ Wlin) {
    int h = threadIdx.x;
    float acc[N_OUT];
    #pragma unroll
    for (int c = 0; c < N_OUT; c++) acc[c] = 0.f;
    for (int k = 0; k < HID; k++) {
        float w = W2[h * HID + k];
        #pragma unroll
        for (int c = 0; c < N_OUT; c++) acc[c] += w * Wlin[k * N_OUT + c];
    }
    #pragma unroll
    for (int c = 0; c < N_OUT; c++) d_M[h * N_OUT + c] = acc[c];
}

__global__ void pool_kernel(const int* __restrict__ batch) {
    int n = blockIdx.x * blockDim.x + threadIdx.x;
    if (n >= N_NODES) return;
    float acc[N_OUT];
    #pragma unroll
    for (int c = 0; c < N_OUT; c++) acc[c] = 0.f;
    int beg = d_rowptr[n], end = d_rowptr[n + 1];
    for (int e = beg; e < end; e++) {
        int s = d_colsrc[e];
        float ws = d_invsqrt[s];
        const float* yp = d_y + (size_t)s * N_OUT;
        #pragma unroll
        for (int c = 0; c < N_OUT; c++) acc[c] += ws * yp[c];
    }
    float isn = d_invsqrt[n];
    const float* yn = d_y + (size_t)n * N_OUT;
    int g = batch[n];
    float sc = d_invcnt[g];
    #pragma unroll
    for (int c = 0; c < N_OUT; c++) {
        float z = acc[c] * isn + isn * isn * yn[c];
        atomicAdd(&d_P[g * N_OUT + c], z * sc);
    }
}

__global__ void final_kernel(const float* __restrict__ b2,
                             const float* __restrict__ Wlin,
                             const float* __restrict__ blin,
                             float* __restrict__ out) {
    int idx = blockIdx.x * blockDim.x + threadIdx.x;
    if (idx >= N_G * N_OUT) return;
    int c = idx % N_OUT;
    float b2w = 0.f;
    for (int k = 0; k < HID; k++) b2w += b2[k] * Wlin[k * N_OUT + c];
    out[idx] = d_P[idx] / 15.0f + b2w + blin[c];
}

// ---------------- launch ----------------
extern "C" void kernel_launch(void* const* d_in, const int* in_sizes, int n_in,
                              void* d_out, int out_size) {
    const float *x = 0, *W1 = 0, *W2 = 0, *b2 = 0, *Wlin = 0, *blin = 0;
    const int *src = 0, *dst = 0, *batch = 0;
    for (int i = 0; i < n_in; i++) {
        int s = in_sizes[i];
        void* p = d_in[i];
        if (s == N_NODES * F_IN)       x = (const float*)p;
        else if (s == F_IN * HID)      W1 = (const float*)p;
        else if (s == HID * HID)       W2 = (const float*)p;
        else if (s == HID)             b2 = (const float*)p;
        else if (s == HID * N_OUT)     Wlin = (const float*)p;
        else if (s == N_OUT)           blin = (const float*)p;
        else if (s == N_EDGES)         { if (!src) src = (const int*)p; else dst = (const int*)p; }
        else if (s == N_NODES)         batch = (const int*)p;
    }

    Keys keys;
    for (int t = 0; t < T_STEPS; t++) {
        uint32_t o0, o1;
        threefry_pair_host(0u, 42u, 0u, (uint32_t)t, &o0, &o1);
        keys.k0[t] = o0; keys.k1[t] = o1;
    }

    cudaFuncSetAttribute(fused_kernel, cudaFuncAttributeMaxDynamicSharedMemorySize, SMEM_TOTAL);

    init_kernel<<<(N_NODES + 255) / 256, 256>>>();
    count_deg<<<(N_EDGES + 255) / 256, 256>>>(dst);
    count_batch<<<(N_NODES + 255) / 256, 256>>>(batch);
    node_prep<<<(N_NODES + 255) / 256, 256>>>();
    graph_prep<<<1, 128>>>();
    scan_kernel<<<1, 1024>>>();
    csr_fill<<<(N_EDGES + 255) / 256, 256>>>(src, dst);
    w1pack_kernel<<<32, 256>>>(W1);

    {
        int total = T_STEPS * N_NODES * 4;
        rng_kernel<<<(total + 255) / 256, 256>>>(x, keys);
    }

    mk_kernel<<<1, 256>>>(W2, Wlin);
    fused_kernel<<<N_TILES, 512, SMEM_TOTAL>>>();
    pool_kernel<<<(N_NODES + 255) / 256, 256>>>(batch);
    final_kernel<<<(N_G * N_OUT + 255) / 256, 256>>>(b2, Wlin, blin, (float*)d_out);
}

// round 6
// speedup vs baseline: 1.8298x; 1.1157x over previous
#include <cuda_runtime.h>
#include <cuda_bf16.h>
#include <stdint.h>
#include <math.h>

#define N_NODES 50000
#define N_EDGES 800000
#define F_IN    128
#define HID     256
#define N_OUT   10
#define N_G     128
#define T_STEPS 15
#define TILE    128
#define N_TILES 391   // ceil(50000/128)

// ---------------- device scratch ----------------
__device__ uint4  d_xtbits4[(size_t)T_STEPS * N_NODES];  // 12 MB bitpacked x_t
__device__ uint4  d_W1q[8192];                           // 128KB packed bf16 hi/lo fragments
__device__ int    d_degcnt[N_NODES];
__device__ int    d_rowptr[N_NODES + 1];
__device__ int    d_cursor[N_NODES];
__device__ int    d_colsrc[N_EDGES];
__device__ float  d_invdeg[N_NODES];
__device__ float  d_invsqrt[N_NODES];
__device__ int    d_gcnt[N_G];
__device__ float  d_invcnt[N_G];
__device__ float  d_M[HID * N_OUT];
__device__ float  d_y[(size_t)N_NODES * N_OUT];
__device__ float  d_P[N_G * N_OUT];

struct Keys { unsigned k0[T_STEPS]; unsigned k1[T_STEPS]; };

// ---------------- host threefry for subkeys ----------------
static void threefry_pair_host(uint32_t k0, uint32_t k1, uint32_t x0, uint32_t x1,
                               uint32_t* o0, uint32_t* o1) {
    uint32_t ks2 = k0 ^ k1 ^ 0x1BD11BDAu;
    x0 += k0; x1 += k1;
#define HR(R) { x0 += x1; x1 = (x1 << R) | (x1 >> (32 - R)); x1 ^= x0; }
    HR(13) HR(15) HR(26) HR(6)
    x0 += k1; x1 += ks2 + 1u;
    HR(17) HR(29) HR(16) HR(24)
    x0 += ks2; x1 += k0 + 2u;
    HR(13) HR(15) HR(26) HR(6)
    x0 += k0; x1 += k1 + 3u;
    HR(17) HR(29) HR(16) HR(24)
    x0 += k1; x1 += ks2 + 4u;
    HR(13) HR(15) HR(26) HR(6)
    x0 += ks2; x1 += k0 + 5u;
#undef HR
    *o0 = x0; *o1 = x1;
}

// ---------------- prep kernels ----------------
__global__ void init_kernel() {
    int i = blockIdx.x * blockDim.x + threadIdx.x;
    if (i < N_NODES) { d_degcnt[i] = 0; d_cursor[i] = 0; }
    if (i < N_G)     d_gcnt[i] = 0;
    if (i < N_G * N_OUT) d_P[i] = 0.f;
}

__global__ void counts_kernel(const int* __restrict__ dst, const int* __restrict__ batch) {
    int e = blockIdx.x * blockDim.x + threadIdx.x;
    if (e < N_EDGES) atomicAdd(&d_degcnt[dst[e]], 1);
    if (e < N_NODES) atomicAdd(&d_gcnt[batch[e]], 1);
}

__global__ void preps_kernel() {
    int n = blockIdx.x * blockDim.x + threadIdx.x;
    if (n < N_NODES) {
        int c = d_degcnt[n];
        int cm = c > 1 ? c : 1;
        d_invdeg[n] = 1.0f / (float)cm;
        d_invsqrt[n] = 1.0f / sqrtf((float)(c + 1));
    }
    if (n < N_G) {
        int c = d_gcnt[n];
        d_invcnt[n] = 1.0f / (float)(c > 1 ? c : 1);
    }
}

// warp-shuffle exclusive scan of d_degcnt -> d_rowptr, single block of 1024
__global__ void scan_kernel() {
    __shared__ int warp_sums[32];
    __shared__ int carry_s;
    int tid = threadIdx.x, lane = tid & 31, w = tid >> 5;
    if (tid == 0) carry_s = 0;
    __syncthreads();
    for (int base = 0; base < N_NODES; base += 1024) {
        int i = base + tid;
        int v = (i < N_NODES) ? d_degcnt[i] : 0;
        int x = v;
        #pragma unroll
        for (int off = 1; off < 32; off <<= 1) {
            int y = __shfl_up_sync(0xFFFFFFFFu, x, off);
            if (lane >= off) x += y;
        }
        if (lane == 31) warp_sums[w] = x;
        __syncthreads();
        if (w == 0) {
            int s = warp_sums[lane];
            #pragma unroll
            for (int off = 1; off < 32; off <<= 1) {
                int y = __shfl_up_sync(0xFFFFFFFFu, s, off);
                if (lane >= off) s += y;
            }
            warp_sums[lane] = s;
        }
        __syncthreads();
        int pre = (w > 0 ? warp_sums[w - 1] : 0) + (x - v) + carry_s;
        if (i < N_NODES) d_rowptr[i] = pre;
        int tot = warp_sums[31];
        __syncthreads();
        if (tid == 0) carry_s += tot;
        __syncthreads();
    }
    if (tid == 0) d_rowptr[N_NODES] = carry_s;
}

__global__ void csr_fill(const int* __restrict__ src, const int* __restrict__ dst) {
    int e = blockIdx.x * blockDim.x + threadIdx.x;
    if (e >= N_EDGES) return;
    int d = dst[e];
    int p = atomicAdd(&d_cursor[d], 1);
    d_colsrc[d_rowptr[d] + p] = src[e];
}

// ---------------- W1 pack: per (j, ks, q) -> uint4 {hi_b0, hi_b1, lo_b0, lo_b1} ----------------
__device__ __forceinline__ unsigned short f2bf_hi(float w) {
    return (unsigned short)__bfloat16_as_ushort(__float2bfloat16(w));
}

__global__ void w1pack_kernel(const float* __restrict__ W1) {
    int idx = blockIdx.x * blockDim.x + threadIdx.x;   // 8192 = 256 j * 8 ks * 4 q
    if (idx >= 8192) return;
    int q = idx & 3, ks = (idx >> 2) & 7, j = idx >> 5;
    int k0 = ks * 16;
    int ka = k0 + 2 * q;
    int kb = k0 + 8 + 2 * q;
    float wa0 = W1[ka * HID + j],       wa1 = W1[(ka + 1) * HID + j];
    float wb0 = W1[kb * HID + j],       wb1 = W1[(kb + 1) * HID + j];
    unsigned short ha0 = f2bf_hi(wa0), ha1 = f2bf_hi(wa1);
    unsigned short hb0 = f2bf_hi(wb0), hb1 = f2bf_hi(wb1);
    float ra0 = wa0 - __bfloat162float(__ushort_as_bfloat16(ha0));
    float ra1 = wa1 - __bfloat162float(__ushort_as_bfloat16(ha1));
    float rb0 = wb0 - __bfloat162float(__ushort_as_bfloat16(hb0));
    float rb1 = wb1 - __bfloat162float(__ushort_as_bfloat16(hb1));
    unsigned short la0 = f2bf_hi(ra0), la1 = f2bf_hi(ra1);
    unsigned short lb0 = f2bf_hi(rb0), lb1 = f2bf_hi(rb1);
    uint4 o;
    o.x = (unsigned)ha0 | ((unsigned)ha1 << 16);
    o.y = (unsigned)hb0 | ((unsigned)hb1 << 16);
    o.z = (unsigned)la0 | ((unsigned)la1 << 16);
    o.w = (unsigned)lb0 | ((unsigned)lb1 << 16);
    d_W1q[idx] = o;
}

// ---------------- RNG: JAX threefry2x32 partitionable ----------------
#define DR(R) { x0 += x1; x1 = __funnelshift_l(x1, x1, R); x1 ^= x0; }

__global__ void rng_kernel(const float* __restrict__ x, Keys keys) {
    int gid = blockIdx.x * blockDim.x + threadIdx.x;
    const int total = T_STEPS * N_NODES * 4;
    if (gid >= total) return;
    int w  = gid & 3;
    int nw = gid >> 2;
    int n  = nw % N_NODES;
    int t  = nw / N_NODES;
    const unsigned k0 = keys.k0[t];
    const unsigned k1 = keys.k1[t];
    const unsigned ks2 = k0 ^ k1 ^ 0x1BD11BDAu;
    const unsigned base = (unsigned)(n * F_IN + w * 32);
    const float* xr = x + n * F_IN + w * 32;
    unsigned outw = 0u;
    #pragma unroll 4
    for (int b = 0; b < 32; b++) {
        unsigned x0 = k0;
        unsigned x1 = base + (unsigned)b + k1;
        DR(13) DR(15) DR(26) DR(6)
        x0 += k1;  x1 += ks2 + 1u;
        DR(17) DR(29) DR(16) DR(24)
        x0 += ks2; x1 += k0 + 2u;
        DR(13) DR(15) DR(26) DR(6)
        x0 += k0;  x1 += k1 + 3u;
        DR(17) DR(29) DR(16) DR(24)
        x0 += k1;  x1 += ks2 + 4u;
        DR(13) DR(15) DR(26) DR(6)
        x0 += ks2; x1 += k0 + 5u;
        unsigned bits = x0 ^ x1;
        float u = __uint_as_float((bits >> 9) | 0x3f800000u) - 1.0f;
        if (u < xr[b]) outw |= (1u << b);
    }
    ((unsigned*)d_xtbits4)[gid] = outw;
}
#undef DR

// ---------------- warp-mma helpers ----------------
__device__ __forceinline__ void mma_bf16(float* d, const unsigned* a, unsigned b0, unsigned b1) {
    asm volatile(
        "mma.sync.aligned.m16n8k16.row.col.f32.bf16.bf16.f32 "
        "{%0,%1,%2,%3}, {%4,%5,%6,%7}, {%8,%9}, {%0,%1,%2,%3};"
        : "+f"(d[0]), "+f"(d[1]), "+f"(d[2]), "+f"(d[3])
        : "r"(a[0]), "r"(a[1]), "r"(a[2]), "r"(a[3]), "r"(b0), "r"(b1));
}

__device__ __forceinline__ void ldmatrix4(unsigned* r, uint32_t addr) {
    asm volatile("ldmatrix.sync.aligned.m8n8.x4.shared.b16 {%0,%1,%2,%3}, [%4];"
        : "=r"(r[0]), "=r"(r[1]), "=r"(r[2]), "=r"(r[3]) : "r"(addr));
}

// ---------------- fused time-loop megakernel ----------------
// static smem (34816 B): A counts bf16 [128][136] during t-loop;
// after loop reused: M [2560 f32] @0, yacc [1280 f32] @10240
#define A_STRIDE 136
#define SMEM_BYTES (TILE * A_STRIDE * 2)

__global__ __launch_bounds__(512) void fused_kernel() {
    __shared__ char smem[SMEM_BYTES];
    unsigned short* Aimg = (unsigned short*)smem;
    const int tid = threadIdx.x;
    const int wid = tid >> 5, lane = tid & 31;
    const int tile0 = blockIdx.x * TILE;
    const int rg = wid >> 2, cg = wid & 3;
    const int q = lane & 3, l4 = lane >> 2;

    uint32_t sbA;
    asm("{ .reg .u64 t; cvta.to.shared.u64 t, %1; cvt.u32.u64 %0, t; }" : "=r"(sbA) : "l"(smem));

    // per-lane rows: r -> row = rg*32 + (r>>1)*16 + (r&1)*8 + l4
    // carry factor: v' = (count + deg*v) * (0.5*invdeg)  ==  0.5*h + 0.5*v
    float hidg[4], dcar[4];
    #pragma unroll
    for (int r = 0; r < 4; r++) {
        int lr = rg * 32 + (r >> 1) * 16 + (r & 1) * 8 + l4;
        int n = tile0 + lr;
        if (n < N_NODES) {
            int c = d_degcnt[n];
            int cm = c > 1 ? c : 1;
            hidg[r] = 0.5f * d_invdeg[n];
            dcar[r] = (float)cm;               // FIXED: was 2*cm (no leak) -> deg
        } else { hidg[r] = 0.f; dcar[r] = 0.f; }
    }

    unsigned Spk[8];
    #pragma unroll
    for (int i = 0; i < 8; i++) Spk[i] = 0u;

    // acc doubles as membrane state: acc = count + deg*v ; starts at v=0
    float acc[2][8][4];
    #pragma unroll
    for (int rb = 0; rb < 2; rb++)
        #pragma unroll
        for (int nt = 0; nt < 8; nt++)
            #pragma unroll
            for (int k = 0; k < 4; k++) acc[rb][nt][k] = 0.f;

    const uint32_t aAddr0 = sbA + (uint32_t)(((rg * 32 + (lane & 15)) * A_STRIDE + (lane >> 4) * 8) * 2);
    const uint32_t aAddr1 = aAddr0 + 16 * A_STRIDE * 2;

    for (int t = 0; t < T_STEPS; t++) {
        // ---- aggregation: warp wid handles nodes [wid*8, wid*8+8), MLP=8 ----
        const uint4* xb = d_xtbits4 + (size_t)t * N_NODES;
        #pragma unroll 1
        for (int i = 0; i < 8; i++) {
            int m = wid * 8 + i;
            int n = tile0 + m;
            int c0 = 0, c1 = 0, c2 = 0, c3 = 0;
            if (n < N_NODES) {
                int beg = __ldg(&d_rowptr[n]), end = __ldg(&d_rowptr[n + 1]);
                int e = beg;
                for (; e + 8 <= end; e += 8) {
                    int s0 = __ldg(&d_colsrc[e]),     s1 = __ldg(&d_colsrc[e + 1]);
                    int s2 = __ldg(&d_colsrc[e + 2]), s3 = __ldg(&d_colsrc[e + 3]);
                    int s4 = __ldg(&d_colsrc[e + 4]), s5 = __ldg(&d_colsrc[e + 5]);
                    int s6 = __ldg(&d_colsrc[e + 6]), s7 = __ldg(&d_colsrc[e + 7]);
                    uint4 w0 = __ldg(xb + s0), w1 = __ldg(xb + s1);
                    uint4 w2 = __ldg(xb + s2), w3 = __ldg(xb + s3);
                    uint4 w4 = __ldg(xb + s4), w5 = __ldg(xb + s5);
                    uint4 w6 = __ldg(xb + s6), w7 = __ldg(xb + s7);
                    c0 += ((w0.x >> lane) & 1) + ((w1.x >> lane) & 1) + ((w2.x >> lane) & 1) + ((w3.x >> lane) & 1)
                        + ((w4.x >> lane) & 1) + ((w5.x >> lane) & 1) + ((w6.x >> lane) & 1) + ((w7.x >> lane) & 1);
                    c1 += ((w0.y >> lane) & 1) + ((w1.y >> lane) & 1) + ((w2.y >> lane) & 1) + ((w3.y >> lane) & 1)
                        + ((w4.y >> lane) & 1) + ((w5.y >> lane) & 1) + ((w6.y >> lane) & 1) + ((w7.y >> lane) & 1);
                    c2 += ((w0.z >> lane) & 1) + ((w1.z >> lane) & 1) + ((w2.z >> lane) & 1) + ((w3.z >> lane) & 1)
                        + ((w4.z >> lane) & 1) + ((w5.z >> lane) & 1) + ((w6.z >> lane) & 1) + ((w7.z >> lane) & 1);
                    c3 += ((w0.w >> lane) & 1) + ((w1.w >> lane) & 1) + ((w2.w >> lane) & 1) + ((w3.w >> lane) & 1)
                        + ((w4.w >> lane) & 1) + ((w5.w >> lane) & 1) + ((w6.w >> lane) & 1) + ((w7.w >> lane) & 1);
                }
                for (; e < end; e++) {
                    uint4 wv = __ldg(xb + __ldg(&d_colsrc[e]));
                    c0 += (wv.x >> lane) & 1;
                    c1 += (wv.y >> lane) & 1;
                    c2 += (wv.z >> lane) & 1;
                    c3 += (wv.w >> lane) & 1;
                }
            }
            // exact small ints -> bf16 (truncation exact for counts <= 256)
            Aimg[m * A_STRIDE + lane]      = (unsigned short)(__float_as_uint((float)c0) >> 16);
            Aimg[m * A_STRIDE + 32 + lane] = (unsigned short)(__float_as_uint((float)c1) >> 16);
            Aimg[m * A_STRIDE + 64 + lane] = (unsigned short)(__float_as_uint((float)c2) >> 16);
            Aimg[m * A_STRIDE + 96 + lane] = (unsigned short)(__float_as_uint((float)c3) >> 16);
        }
        __syncthreads();

        // ---- warp GEMM accumulating onto acc (= deg*v carried in) ----
        #pragma unroll
        for (int ks = 0; ks < 8; ks++) {
            unsigned a0[4], a1[4];
            ldmatrix4(a0, aAddr0 + (uint32_t)(ks * 32));
            ldmatrix4(a1, aAddr1 + (uint32_t)(ks * 32));
            #pragma unroll
            for (int nt = 0; nt < 8; nt++) {
                int j = cg * 64 + nt * 8 + l4;
                uint4 B = __ldg(&d_W1q[(j * 8 + ks) * 4 + q]);
                mma_bf16(acc[0][nt], a0, B.x, B.y);
                mma_bf16(acc[1][nt], a1, B.x, B.y);
                mma_bf16(acc[0][nt], a0, B.z, B.w);
                mma_bf16(acc[1][nt], a1, B.z, B.w);
            }
        }

        // ---- LIF epilogue fully in registers ----
        #pragma unroll
        for (int rb = 0; rb < 2; rb++) {
            #pragma unroll
            for (int nt = 0; nt < 8; nt++) {
                #pragma unroll
                for (int h8 = 0; h8 < 2; h8++) {
                    const int r = rb * 2 + h8;
                    #pragma unroll
                    for (int p = 0; p < 2; p++) {
                        float vn = acc[rb][nt][h8 * 2 + p] * hidg[r];
                        const int slot = r * 16 + nt * 2 + p;
                        if (vn >= 0.25f) { Spk[slot >> 3] += 1u << ((slot & 7) * 4); vn = 0.f; }
                        acc[rb][nt][h8 * 2 + p] = vn * dcar[r];
                    }
                }
            }
        }
        __syncthreads();
    }

    // ---- fused readout: y = S @ M ----
    float* Msm  = (float*)smem;               // 2560 f32 (A region dead)
    float* yacc = (float*)(smem + 10240);     // 1280 f32
    for (int i = tid; i < HID * N_OUT; i += 512) Msm[i] = d_M[i];
    for (int i = tid; i < TILE * N_OUT; i += 512) yacc[i] = 0.f;
    __syncthreads();

    #pragma unroll
    for (int r = 0; r < 4; r++) {
        float py[N_OUT];
        #pragma unroll
        for (int c = 0; c < N_OUT; c++) py[c] = 0.f;
        #pragma unroll
        for (int nt = 0; nt < 8; nt++) {
            #pragma unroll
            for (int p = 0; p < 2; p++) {
                const int slot = r * 16 + nt * 2 + p;
                float s = (float)((Spk[slot >> 3] >> ((slot & 7) * 4)) & 15u);
                const float* Mr = Msm + (cg * 64 + nt * 8 + q * 2 + p) * N_OUT;
                #pragma unroll
                for (int c = 0; c < N_OUT; c++) py[c] += s * Mr[c];
            }
        }
        #pragma unroll
        for (int c = 0; c < N_OUT; c++) {
            py[c] += __shfl_xor_sync(0xFFFFFFFFu, py[c], 1);
            py[c] += __shfl_xor_sync(0xFFFFFFFFu, py[c], 2);
        }
        if (q == 0) {
            int lr = rg * 32 + (r >> 1) * 16 + (r & 1) * 8 + l4;
            #pragma unroll
            for (int c = 0; c < N_OUT; c++)
                atomicAdd(&yacc[lr * N_OUT + c], py[c]);
        }
    }
    __syncthreads();

    for (int i = tid; i < TILE * N_OUT; i += 512) {
        int node = tile0 + i / N_OUT;
        if (node < N_NODES) d_y[(size_t)node * N_OUT + (i % N_OUT)] = yacc[i];
    }
}

// ---------------- readout helpers ----------------
__global__ void mk_kernel(const float* __restrict__ W2, const float* __restrict__ Wlin) {
    int h = threadIdx.x;
    float acc[N_OUT];
    #pragma unroll
    for (int c = 0; c < N_OUT; c++) acc[c] = 0.f;
    for (int k = 0; k < HID; k++) {
        float w = W2[h * HID + k];
        #pragma unroll
        for (int c = 0; c < N_OUT; c++) acc[c] += w * Wlin[k * N_OUT + c];
    }
    #pragma unroll
    for (int c = 0; c < N_OUT; c++) d_M[h * N_OUT + c] = acc[c];
}

__global__ void pool_kernel(const int* __restrict__ batch) {
    int n = blockIdx.x * blockDim.x + threadIdx.x;
    if (n >= N_NODES) return;
    float acc[N_OUT];
    #pragma unroll
    for (int c = 0; c < N_OUT; c++) acc[c] = 0.f;
    int beg = d_rowptr[n], end = d_rowptr[n + 1];
    for (int e = beg; e < end; e++) {
        int s = d_colsrc[e];
        float ws = d_invsqrt[s];
        const float* yp = d_y + (size_t)s * N_OUT;
        #pragma unroll
        for (int c = 0; c < N_OUT; c++) acc[c] += ws * yp[c];
    }
    float isn = d_invsqrt[n];
    const float* yn = d_y + (size_t)n * N_OUT;
    int g = batch[n];
    float sc = d_invcnt[g];
    #pragma unroll
    for (int c = 0; c < N_OUT; c++) {
        float z = acc[c] * isn + isn * isn * yn[c];
        atomicAdd(&d_P[g * N_OUT + c], z * sc);
    }
}

__global__ void final_kernel(const float* __restrict__ b2,
                             const float* __restrict__ Wlin,
                             const float* __restrict__ blin,
                             float* __restrict__ out) {
    int idx = blockIdx.x * blockDim.x + threadIdx.x;
    if (idx >= N_G * N_OUT) return;
    int c = idx % N_OUT;
    float b2w = 0.f;
    for (int k = 0; k < HID; k++) b2w += b2[k] * Wlin[k * N_OUT + c];
    out[idx] = d_P[idx] / 15.0f + b2w + blin[c];
}

// ---------------- launch ----------------
extern "C" void kernel_launch(void* const* d_in, const int* in_sizes, int n_in,
                              void* d_out, int out_size) {
    const float *x = 0, *W1 = 0, *W2 = 0, *b2 = 0, *Wlin = 0, *blin = 0;
    const int *src = 0, *dst = 0, *batch = 0;
    for (int i = 0; i < n_in; i++) {
        int s = in_sizes[i];
        void* p = d_in[i];
        if (s == N_NODES * F_IN)       x = (const float*)p;
        else if (s == F_IN * HID)      W1 = (const float*)p;
        else if (s == HID * HID)       W2 = (const float*)p;
        else if (s == HID)             b2 = (const float*)p;
        else if (s == HID * N_OUT)     Wlin = (const float*)p;
        else if (s == N_OUT)           blin = (const float*)p;
        else if (s == N_EDGES)         { if (!src) src = (const int*)p; else dst = (const int*)p; }
        else if (s == N_NODES)         batch = (const int*)p;
    }

    Keys keys;
    for (int t = 0; t < T_STEPS; t++) {
        uint32_t o0, o1;
        threefry_pair_host(0u, 42u, 0u, (uint32_t)t, &o0, &o1);
        keys.k0[t] = o0; keys.k1[t] = o1;
    }

    init_kernel<<<(N_NODES + 255) / 256, 256>>>();
    counts_kernel<<<(N_EDGES + 255) / 256, 256>>>(dst, batch);
    preps_kernel<<<(N_NODES + 255) / 256, 256>>>();
    scan_kernel<<<1, 1024>>>();
    csr_fill<<<(N_EDGES + 255) / 256, 256>>>(src, dst);
    w1pack_kernel<<<32, 256>>>(W1);

    {
        int total = T_STEPS * N_NODES * 4;
        rng_kernel<<<(total + 255) / 256, 256>>>(x, keys);
    }

    mk_kernel<<<1, 256>>>(W2, Wlin);
    fused_kernel<<<N_TILES, 512>>>();
    pool_kernel<<<(N_NODES + 255) / 256, 256>>>(batch);
    final_kernel<<<(N_G * N_OUT + 255) / 256, 256>>>(b2, Wlin, blin, (float*)d_out);
}

// round 7
// speedup vs baseline: 1.8423x; 1.0069x over previous
#include <cuda_runtime.h>
#include <cuda_bf16.h>
#include <stdint.h>
#include <math.h>

#define N_NODES 50000
#define N_EDGES 800000
#define F_IN    128
#define HID     256
#define N_OUT   10
#define N_G     128
#define T_STEPS 15
#define TILE    128
#define N_TILES 391   // ceil(50000/128)

// ---------------- device scratch ----------------
__device__ uint4  d_xtbits4[(size_t)T_STEPS * N_NODES];  // 12 MB bitpacked x_t
__device__ uint4  d_W1q[8192];                           // 128KB packed bf16 hi/lo fragments
__device__ int    d_degcnt[N_NODES];
__device__ int    d_rowptr[N_NODES + 1];
__device__ int    d_cursor[N_NODES];
__device__ int    d_colsrc[N_EDGES];
__device__ float  d_invdeg[N_NODES];
__device__ float  d_invsqrt[N_NODES];
__device__ int    d_gcnt[N_G];
__device__ float  d_invcnt[N_G];
__device__ float  d_M[HID * N_OUT];
__device__ float  d_y[(size_t)N_NODES * N_OUT];
__device__ float  d_P[N_G * N_OUT];

struct Keys { unsigned k0[T_STEPS]; unsigned k1[T_STEPS]; };

// ---------------- host threefry for subkeys ----------------
static void threefry_pair_host(uint32_t k0, uint32_t k1, uint32_t x0, uint32_t x1,
                               uint32_t* o0, uint32_t* o1) {
    uint32_t ks2 = k0 ^ k1 ^ 0x1BD11BDAu;
    x0 += k0; x1 += k1;
#define HR(R) { x0 += x1; x1 = (x1 << R) | (x1 >> (32 - R)); x1 ^= x0; }
    HR(13) HR(15) HR(26) HR(6)
    x0 += k1; x1 += ks2 + 1u;
    HR(17) HR(29) HR(16) HR(24)
    x0 += ks2; x1 += k0 + 2u;
    HR(13) HR(15) HR(26) HR(6)
    x0 += k0; x1 += k1 + 3u;
    HR(17) HR(29) HR(16) HR(24)
    x0 += k1; x1 += ks2 + 4u;
    HR(13) HR(15) HR(26) HR(6)
    x0 += ks2; x1 += k0 + 5u;
#undef HR
    *o0 = x0; *o1 = x1;
}

// ---------------- prep kernels ----------------
__global__ void init_kernel() {
    int i = blockIdx.x * blockDim.x + threadIdx.x;
    if (i < N_NODES) { d_degcnt[i] = 0; d_cursor[i] = 0; }
    if (i < N_G)     d_gcnt[i] = 0;
    if (i < N_G * N_OUT) d_P[i] = 0.f;
}

__global__ void counts_kernel(const int* __restrict__ dst, const int* __restrict__ batch) {
    int e = blockIdx.x * blockDim.x + threadIdx.x;
    if (e < N_EDGES) atomicAdd(&d_degcnt[dst[e]], 1);
    if (e < N_NODES) atomicAdd(&d_gcnt[batch[e]], 1);
}

__global__ void preps_kernel() {
    int n = blockIdx.x * blockDim.x + threadIdx.x;
    if (n < N_NODES) {
        int c = d_degcnt[n];
        int cm = c > 1 ? c : 1;
        d_invdeg[n] = 1.0f / (float)cm;
        d_invsqrt[n] = 1.0f / sqrtf((float)(c + 1));
    }
    if (n < N_G) {
        int c = d_gcnt[n];
        d_invcnt[n] = 1.0f / (float)(c > 1 ? c : 1);
    }
}

// warp-shuffle exclusive scan of d_degcnt -> d_rowptr, single block of 1024
__global__ void scan_kernel() {
    __shared__ int warp_sums[32];
    __shared__ int carry_s;
    int tid = threadIdx.x, lane = tid & 31, w = tid >> 5;
    if (tid == 0) carry_s = 0;
    __syncthreads();
    for (int base = 0; base < N_NODES; base += 1024) {
        int i = base + tid;
        int v = (i < N_NODES) ? d_degcnt[i] : 0;
        int x = v;
        #pragma unroll
        for (int off = 1; off < 32; off <<= 1) {
            int y = __shfl_up_sync(0xFFFFFFFFu, x, off);
            if (lane >= off) x += y;
        }
        if (lane == 31) warp_sums[w] = x;
        __syncthreads();
        if (w == 0) {
            int s = warp_sums[lane];
            #pragma unroll
            for (int off = 1; off < 32; off <<= 1) {
                int y = __shfl_up_sync(0xFFFFFFFFu, s, off);
                if (lane >= off) s += y;
            }
            warp_sums[lane] = s;
        }
        __syncthreads();
        int pre = (w > 0 ? warp_sums[w - 1] : 0) + (x - v) + carry_s;
        if (i < N_NODES) d_rowptr[i] = pre;
        int tot = warp_sums[31];
        __syncthreads();
        if (tid == 0) carry_s += tot;
        __syncthreads();
    }
    if (tid == 0) d_rowptr[N_NODES] = carry_s;
}

__global__ void csr_fill(const int* __restrict__ src, const int* __restrict__ dst) {
    int e = blockIdx.x * blockDim.x + threadIdx.x;
    if (e >= N_EDGES) return;
    int d = dst[e];
    int p = atomicAdd(&d_cursor[d], 1);
    d_colsrc[d_rowptr[d] + p] = src[e];
}

// ---------------- W1 pack: per (j, ks, q) -> uint4 {hi_b0, hi_b1, lo_b0, lo_b1} ----------------
__device__ __forceinline__ unsigned short f2bf_hi(float w) {
    return (unsigned short)__bfloat16_as_ushort(__float2bfloat16(w));
}

__global__ void w1pack_kernel(const float* __restrict__ W1) {
    int idx = blockIdx.x * blockDim.x + threadIdx.x;   // 8192 = 256 j * 8 ks * 4 q
    if (idx >= 8192) return;
    int q = idx & 3, ks = (idx >> 2) & 7, j = idx >> 5;
    int k0 = ks * 16;
    int ka = k0 + 2 * q;
    int kb = k0 + 8 + 2 * q;
    float wa0 = W1[ka * HID + j],       wa1 = W1[(ka + 1) * HID + j];
    float wb0 = W1[kb * HID + j],       wb1 = W1[(kb + 1) * HID + j];
    unsigned short ha0 = f2bf_hi(wa0), ha1 = f2bf_hi(wa1);
    unsigned short hb0 = f2bf_hi(wb0), hb1 = f2bf_hi(wb1);
    float ra0 = wa0 - __bfloat162float(__ushort_as_bfloat16(ha0));
    float ra1 = wa1 - __bfloat162float(__ushort_as_bfloat16(ha1));
    float rb0 = wb0 - __bfloat162float(__ushort_as_bfloat16(hb0));
    float rb1 = wb1 - __bfloat162float(__ushort_as_bfloat16(hb1));
    unsigned short la0 = f2bf_hi(ra0), la1 = f2bf_hi(ra1);
    unsigned short lb0 = f2bf_hi(rb0), lb1 = f2bf_hi(rb1);
    uint4 o;
    o.x = (unsigned)ha0 | ((unsigned)ha1 << 16);
    o.y = (unsigned)hb0 | ((unsigned)hb1 << 16);
    o.z = (unsigned)la0 | ((unsigned)la1 << 16);
    o.w = (unsigned)lb0 | ((unsigned)lb1 << 16);
    d_W1q[idx] = o;
}

// ---------------- RNG: JAX threefry2x32 partitionable ----------------
#define DR(R) { x0 += x1; x1 = __funnelshift_l(x1, x1, R); x1 ^= x0; }

__global__ void rng_kernel(const float* __restrict__ x, Keys keys) {
    int gid = blockIdx.x * blockDim.x + threadIdx.x;
    const int total = T_STEPS * N_NODES * 4;
    if (gid >= total) return;
    int w  = gid & 3;
    int nw = gid >> 2;
    int n  = nw % N_NODES;
    int t  = nw / N_NODES;
    const unsigned k0 = keys.k0[t];
    const unsigned k1 = keys.k1[t];
    const unsigned ks2 = k0 ^ k1 ^ 0x1BD11BDAu;
    const unsigned base = (unsigned)(n * F_IN + w * 32);
    const float* xr = x + n * F_IN + w * 32;
    unsigned outw = 0u;
    #pragma unroll 4
    for (int b = 0; b < 32; b++) {
        unsigned x0 = k0;
        unsigned x1 = base + (unsigned)b + k1;
        DR(13) DR(15) DR(26) DR(6)
        x0 += k1;  x1 += ks2 + 1u;
        DR(17) DR(29) DR(16) DR(24)
        x0 += ks2; x1 += k0 + 2u;
        DR(13) DR(15) DR(26) DR(6)
        x0 += k0;  x1 += k1 + 3u;
        DR(17) DR(29) DR(16) DR(24)
        x0 += k1;  x1 += ks2 + 4u;
        DR(13) DR(15) DR(26) DR(6)
        x0 += ks2; x1 += k0 + 5u;
        unsigned bits = x0 ^ x1;
        float u = __uint_as_float((bits >> 9) | 0x3f800000u) - 1.0f;
        if (u < xr[b]) outw |= (1u << b);
    }
    ((unsigned*)d_xtbits4)[gid] = outw;
}
#undef DR

// ---------------- warp-mma helpers ----------------
__device__ __forceinline__ void mma_bf16(float* d, const unsigned* a, unsigned b0, unsigned b1) {
    asm volatile(
        "mma.sync.aligned.m16n8k16.row.col.f32.bf16.bf16.f32 "
        "{%0,%1,%2,%3}, {%4,%5,%6,%7}, {%8,%9}, {%0,%1,%2,%3};"
        : "+f"(d[0]), "+f"(d[1]), "+f"(d[2]), "+f"(d[3])
        : "r"(a[0]), "r"(a[1]), "r"(a[2]), "r"(a[3]), "r"(b0), "r"(b1));
}

__device__ __forceinline__ void ldmatrix4(unsigned* r, uint32_t addr) {
    asm volatile("ldmatrix.sync.aligned.m8n8.x4.shared.b16 {%0,%1,%2,%3}, [%4];"
        : "=r"(r[0]), "=r"(r[1]), "=r"(r[2]), "=r"(r[3]) : "r"(addr));
}

// ---------------- fused time-loop megakernel ----------------
// static smem (34816 B): A counts bf16 [128][136] during t-loop;
// after loop reused: M [2560 f32] @0, yacc [1280 f32] @10240
#define A_STRIDE 136
#define SMEM_BYTES (TILE * A_STRIDE * 2)

__global__ __launch_bounds__(512) void fused_kernel() {
    __shared__ char smem[SMEM_BYTES];
    unsigned short* Aimg = (unsigned short*)smem;
    const int tid = threadIdx.x;
    const int wid = tid >> 5, lane = tid & 31;
    const int tile0 = blockIdx.x * TILE;
    const int rg = wid >> 2, cg = wid & 3;
    const int q = lane & 3, l4 = lane >> 2;

    uint32_t sbA;
    asm("{ .reg .u64 t; cvta.to.shared.u64 t, %1; cvt.u32.u64 %0, t; }" : "=r"(sbA) : "l"(smem));

    // per-lane rows: r -> row = rg*32 + (r>>1)*16 + (r&1)*8 + l4
    // carry factor: v' = (count + deg*v) * (0.5*invdeg)  ==  0.5*h + 0.5*v
    float hidg[4], dcar[4];
    #pragma unroll
    for (int r = 0; r < 4; r++) {
        int lr = rg * 32 + (r >> 1) * 16 + (r & 1) * 8 + l4;
        int n = tile0 + lr;
        if (n < N_NODES) {
            int c = d_degcnt[n];
            int cm = c > 1 ? c : 1;
            hidg[r] = 0.5f * d_invdeg[n];
            dcar[r] = (float)cm;               // FIXED: was 2*cm (no leak) -> deg
        } else { hidg[r] = 0.f; dcar[r] = 0.f; }
    }

    unsigned Spk[8];
    #pragma unroll
    for (int i = 0; i < 8; i++) Spk[i] = 0u;

    // acc doubles as membrane state: acc = count + deg*v ; starts at v=0
    float acc[2][8][4];
    #pragma unroll
    for (int rb = 0; rb < 2; rb++)
        #pragma unroll
        for (int nt = 0; nt < 8; nt++)
            #pragma unroll
            for (int k = 0; k < 4; k++) acc[rb][nt][k] = 0.f;

    const uint32_t aAddr0 = sbA + (uint32_t)(((rg * 32 + (lane & 15)) * A_STRIDE + (lane >> 4) * 8) * 2);
    const uint32_t aAddr1 = aAddr0 + 16 * A_STRIDE * 2;

    for (int t = 0; t < T_STEPS; t++) {
        // ---- aggregation: warp wid handles nodes [wid*8, wid*8+8), MLP=8 ----
        const uint4* xb = d_xtbits4 + (size_t)t * N_NODES;
        #pragma unroll 1
        for (int i = 0; i < 8; i++) {
            int m = wid * 8 + i;
            int n = tile0 + m;
            int c0 = 0, c1 = 0, c2 = 0, c3 = 0;
            if (n < N_NODES) {
                int beg = __ldg(&d_rowptr[n]), end = __ldg(&d_rowptr[n + 1]);
                int e = beg;
                for (; e + 8 <= end; e += 8) {
                    int s0 = __ldg(&d_colsrc[e]),     s1 = __ldg(&d_colsrc[e + 1]);
                    int s2 = __ldg(&d_colsrc[e + 2]), s3 = __ldg(&d_colsrc[e + 3]);
                    int s4 = __ldg(&d_colsrc[e + 4]), s5 = __ldg(&d_colsrc[e + 5]);
                    int s6 = __ldg(&d_colsrc[e + 6]), s7 = __ldg(&d_colsrc[e + 7]);
                    uint4 w0 = __ldg(xb + s0), w1 = __ldg(xb + s1);
                    uint4 w2 = __ldg(xb + s2), w3 = __ldg(xb + s3);
                    uint4 w4 = __ldg(xb + s4), w5 = __ldg(xb + s5);
                    uint4 w6 = __ldg(xb + s6), w7 = __ldg(xb + s7);
                    c0 += ((w0.x >> lane) & 1) + ((w1.x >> lane) & 1) + ((w2.x >> lane) & 1) + ((w3.x >> lane) & 1)
                        + ((w4.x >> lane) & 1) + ((w5.x >> lane) & 1) + ((w6.x >> lane) & 1) + ((w7.x >> lane) & 1);
                    c1 += ((w0.y >> lane) & 1) + ((w1.y >> lane) & 1) + ((w2.y >> lane) & 1) + ((w3.y >> lane) & 1)
                        + ((w4.y >> lane) & 1) + ((w5.y >> lane) & 1) + ((w6.y >> lane) & 1) + ((w7.y >> lane) & 1);
                    c2 += ((w0.z >> lane) & 1) + ((w1.z >> lane) & 1) + ((w2.z >> lane) & 1) + ((w3.z >> lane) & 1)
                        + ((w4.z >> lane) & 1) + ((w5.z >> lane) & 1) + ((w6.z >> lane) & 1) + ((w7.z >> lane) & 1);
                    c3 += ((w0.w >> lane) & 1) + ((w1.w >> lane) & 1) + ((w2.w >> lane) & 1) + ((w3.w >> lane) & 1)
                        + ((w4.w >> lane) & 1) + ((w5.w >> lane) & 1) + ((w6.w >> lane) & 1) + ((w7.w >> lane) & 1);
                }
                for (; e < end; e++) {
                    uint4 wv = __ldg(xb + __ldg(&d_colsrc[e]));
                    c0 += (wv.x >> lane) & 1;
                    c1 += (wv.y >> lane) & 1;
                    c2 += (wv.z >> lane) & 1;
                    c3 += (wv.w >> lane) & 1;
                }
            }
            // exact small ints -> bf16 (truncation exact for counts <= 256)
            Aimg[m * A_STRIDE + lane]      = (unsigned short)(__float_as_uint((float)c0) >> 16);
            Aimg[m * A_STRIDE + 32 + lane] = (unsigned short)(__float_as_uint((float)c1) >> 16);
            Aimg[m * A_STRIDE + 64 + lane] = (unsigned short)(__float_as_uint((float)c2) >> 16);
            Aimg[m * A_STRIDE + 96 + lane] = (unsigned short)(__float_as_uint((float)c3) >> 16);
        }
        __syncthreads();

        // ---- warp GEMM accumulating onto acc (= deg*v carried in) ----
        #pragma unroll
        for (int ks = 0; ks < 8; ks++) {
            unsigned a0[4], a1[4];
            ldmatrix4(a0, aAddr0 + (uint32_t)(ks * 32));
            ldmatrix4(a1, aAddr1 + (uint32_t)(ks * 32));
            #pragma unroll
            for (int nt = 0; nt < 8; nt++) {
                int j = cg * 64 + nt * 8 + l4;
                uint4 B = __ldg(&d_W1q[(j * 8 + ks) * 4 + q]);
                mma_bf16(acc[0][nt], a0, B.x, B.y);
                mma_bf16(acc[1][nt], a1, B.x, B.y);
                mma_bf16(acc[0][nt], a0, B.z, B.w);
                mma_bf16(acc[1][nt], a1, B.z, B.w);
            }
        }

        // ---- LIF epilogue fully in registers ----
        #pragma unroll
        for (int rb = 0; rb < 2; rb++) {
            #pragma unroll
            for (int nt = 0; nt < 8; nt++) {
                #pragma unroll
                for (int h8 = 0; h8 < 2; h8++) {
                    const int r = rb * 2 + h8;
                    #pragma unroll
                    for (int p = 0; p < 2; p++) {
                        float vn = acc[rb][nt][h8 * 2 + p] * hidg[r];
                        const int slot = r * 16 + nt * 2 + p;
                        if (vn >= 0.25f) { Spk[slot >> 3] += 1u << ((slot & 7) * 4); vn = 0.f; }
                        acc[rb][nt][h8 * 2 + p] = vn * dcar[r];
                    }
                }
            }
        }
        __syncthreads();
    }

    // ---- fused readout: y = S @ M ----
    float* Msm  = (float*)smem;               // 2560 f32 (A region dead)
    float* yacc = (float*)(smem + 10240);     // 1280 f32
    for (int i = tid; i < HID * N_OUT; i += 512) Msm[i] = d_M[i];
    for (int i = tid; i < TILE * N_OUT; i += 512) yacc[i] = 0.f;
    __syncthreads();

    #pragma unroll
    for (int r = 0; r < 4; r++) {
        float py[N_OUT];
        #pragma unroll
        for (int c = 0; c < N_OUT; c++) py[c] = 0.f;
        #pragma unroll
        for (int nt = 0; nt < 8; nt++) {
            #pragma unroll
            for (int p = 0; p < 2; p++) {
                const int slot = r * 16 + nt * 2 + p;
                float s = (float)((Spk[slot >> 3] >> ((slot & 7) * 4)) & 15u);
                const float* Mr = Msm + (cg * 64 + nt * 8 + q * 2 + p) * N_OUT;
                #pragma unroll
                for (int c = 0; c < N_OUT; c++) py[c] += s * Mr[c];
            }
        }
        #pragma unroll
        for (int c = 0; c < N_OUT; c++) {
            py[c] += __shfl_xor_sync(0xFFFFFFFFu, py[c], 1);
            py[c] += __shfl_xor_sync(0xFFFFFFFFu, py[c], 2);
        }
        if (q == 0) {
            int lr = rg * 32 + (r >> 1) * 16 + (r & 1) * 8 + l4;
            #pragma unroll
            for (int c = 0; c < N_OUT; c++)
                atomicAdd(&yacc[lr * N_OUT + c], py[c]);
        }
    }
    __syncthreads();

    for (int i = tid; i < TILE * N_OUT; i += 512) {
        int node = tile0 + i / N_OUT;
        if (node < N_NODES) d_y[(size_t)node * N_OUT + (i % N_OUT)] = yacc[i];
    }
}

// ---------------- readout helpers ----------------
__global__ void mk_kernel(const float* __restrict__ W2, const float* __restrict__ Wlin) {
    int h = threadIdx.x;
    float acc[N_OUT];
    #pragma unroll
    for (int c = 0; c < N_OUT; c++) acc[c] = 0.f;
    for (int k = 0; k < HID; k++) {
        float w = W2[h * HID + k];
        #pragma unroll
        for (int c = 0; c < N_OUT; c++) acc[c] += w * Wlin[k * N_OUT + c];
    }
    #pragma unroll
    for (int c = 0; c < N_OUT; c++) d_M[h * N_OUT + c] = acc[c];
}

__global__ void pool_kernel(const int* __restrict__ batch) {
    int n = blockIdx.x * blockDim.x + threadIdx.x;
    if (n >= N_NODES) return;
    float acc[N_OUT];
    #pragma unroll
    for (int c = 0; c < N_OUT; c++) acc[c] = 0.f;
    int beg = d_rowptr[n], end = d_rowptr[n + 1];
    for (int e = beg; e < end; e++) {
        int s = d_colsrc[e];
        float ws = d_invsqrt[s];
        const float* yp = d_y + (size_t)s * N_OUT;
        #pragma unroll
        for (int c = 0; c < N_OUT; c++) acc[c] += ws * yp[c];
    }
    float isn = d_invsqrt[n];
    const float* yn = d_y + (size_t)n * N_OUT;
    int g = batch[n];
    float sc = d_invcnt[g];
    #pragma unroll
    for (int c = 0; c < N_OUT; c++) {
        float z = acc[c] * isn + isn * isn * yn[c];
        atomicAdd(&d_P[g * N_OUT + c], z * sc);
    }
}

__global__ void final_kernel(const float* __restrict__ b2,
                             const float* __restrict__ Wlin,
                             const float* __restrict__ blin,
                             float* __restrict__ out) {
    int idx = blockIdx.x * blockDim.x + threadIdx.x;
    if (idx >= N_G * N_OUT) return;
    int c = idx % N_OUT;
    float b2w = 0.f;
    for (int k = 0; k < HID; k++) b2w += b2[k] * Wlin[k * N_OUT + c];
    out[idx] = d_P[idx] / 15.0f + b2w + blin[c];
}

// ---------------- launch ----------------
extern "C" void kernel_launch(void* const* d_in, const int* in_sizes, int n_in,
                              void* d_out, int out_size) {
    const float *x = 0, *W1 = 0, *W2 = 0, *b2 = 0, *Wlin = 0, *blin = 0;
    const int *src = 0, *dst = 0, *batch = 0;
    for (int i = 0; i < n_in; i++) {
        int s = in_sizes[i];
        void* p = d_in[i];
        if (s == N_NODES * F_IN)       x = (const float*)p;
        else if (s == F_IN * HID)      W1 = (const float*)p;
        else if (s == HID * HID)       W2 = (const float*)p;
        else if (s == HID)             b2 = (const float*)p;
        else if (s == HID * N_OUT)     Wlin = (const float*)p;
        else if (s == N_OUT)           blin = (const float*)p;
        else if (s == N_EDGES)         { if (!src) src = (const int*)p; else dst = (const int*)p; }
        else if (s == N_NODES)         batch = (const int*)p;
    }

    Keys keys;
    for (int t = 0; t < T_STEPS; t++) {
        uint32_t o0, o1;
        threefry_pair_host(0u, 42u, 0u, (uint32_t)t, &o0, &o1);
        keys.k0[t] = o0; keys.k1[t] = o1;
    }

    init_kernel<<<(N_NODES + 255) / 256, 256>>>();
    counts_kernel<<<(N_EDGES + 255) / 256, 256>>>(dst, batch);
    preps_kernel<<<(N_NODES + 255) / 256, 256>>>();
    scan_kernel<<<1, 1024>>>();
    csr_fill<<<(N_EDGES + 255) / 256, 256>>>(src, dst);
    w1pack_kernel<<<32, 256>>>(W1);

    {
        int total = T_STEPS * N_NODES * 4;
        rng_kernel<<<(total + 255) / 256, 256>>>(x, keys);
    }

    mk_kernel<<<1, 256>>>(W2, Wlin);
    fused_kernel<<<N_TILES, 512>>>();
    pool_kernel<<<(N_NODES + 255) / 256, 256>>>(batch);
    final_kernel<<<(N_G * N_OUT + 255) / 256, 256>>>(b2, Wlin, blin, (float*)d_out);
}